// round 1
// baseline (speedup 1.0000x reference)
#include <cuda_runtime.h>
#include <cuda_bf16.h>
#include <cstdint>

#define INPUT 256
#define HID   512
#define G4    2048
#define BATCH 256
#define SEQ   512
#define NCLS  128

// ---------------- static scratch (no allocation allowed) ----------------
__device__ float          g_xproj[SEQ * BATCH * G4];   // 1 GiB: [t][b][4H] preactivations (biases folded)
__device__ __nv_bfloat16  g_Whh_bf[G4 * HID];          // bf16 copy of W_hh
__device__ __nv_bfloat16  g_hbuf[2][BATCH * HID];      // double-buffered hidden state (bf16)
__device__ float          g_c[BATCH * HID];            // cell state fp32
__device__ float          g_hlast[BATCH * HID];        // final h in fp32 for the FC

// ---------------- mma helpers ----------------
__device__ __forceinline__ uint32_t f2tf(float f) {
    uint32_t r;
    asm("cvt.rna.tf32.f32 %0, %1;" : "=r"(r) : "f"(f));
    return r;
}

__device__ __forceinline__ void mma_tf32(float c[4], const uint32_t a[4], const uint32_t b[2]) {
    asm volatile(
        "mma.sync.aligned.m16n8k8.row.col.f32.tf32.tf32.f32 "
        "{%0,%1,%2,%3}, {%4,%5,%6,%7}, {%8,%9}, {%0,%1,%2,%3};\n"
        : "+f"(c[0]), "+f"(c[1]), "+f"(c[2]), "+f"(c[3])
        : "r"(a[0]), "r"(a[1]), "r"(a[2]), "r"(a[3]), "r"(b[0]), "r"(b[1]));
}

__device__ __forceinline__ void mma_bf16(float c[4], const uint32_t a[4], const uint32_t b[2]) {
    asm volatile(
        "mma.sync.aligned.m16n8k16.row.col.f32.bf16.bf16.f32 "
        "{%0,%1,%2,%3}, {%4,%5,%6,%7}, {%8,%9}, {%0,%1,%2,%3};\n"
        : "+f"(c[0]), "+f"(c[1]), "+f"(c[2]), "+f"(c[3])
        : "r"(a[0]), "r"(a[1]), "r"(a[2]), "r"(a[3]), "r"(b[0]), "r"(b[1]));
}

// ---------------- setup: convert W_hh to bf16, zero h0/c0 ----------------
__global__ void setup_kernel(const float* __restrict__ Whh) {
    int stride = gridDim.x * blockDim.x;
    for (int i = blockIdx.x * blockDim.x + threadIdx.x; i < G4 * HID; i += stride)
        g_Whh_bf[i] = __float2bfloat16(Whh[i]);
    for (int i = blockIdx.x * blockDim.x + threadIdx.x; i < BATCH * HID; i += stride) {
        g_hbuf[0][i] = __float2bfloat16(0.f);
        g_c[i] = 0.f;
    }
}

// ---------------- phase 1: x_proj GEMM (tf32) ----------------
// C[m, n] = sum_k x[m, k] * W_ih[n, k] + (b_ih[n] + b_hh[n]),  m = b*SEQ + t
// Output stored as g_xproj[t][b][n].
__global__ __launch_bounds__(256) void xproj_kernel(
    const float* __restrict__ x, const float* __restrict__ Wih,
    const float* __restrict__ bih, const float* __restrict__ bhh) {
    __shared__ float As[128][20];   // pad 20 -> conflict-free frag loads
    __shared__ float Bs[128][20];

    const int m0 = blockIdx.y * 128;
    const int n0 = blockIdx.x * 128;
    const int tid = threadIdx.x;
    const int w = tid >> 5, l = tid & 31;
    const int wm = w >> 1, wn = w & 1;       // 4x2 warp grid, warp tile 32x64
    const int lr = l >> 2, lc = l & 3;

    float acc[2][8][4] = {};

    for (int k0 = 0; k0 < INPUT; k0 += 16) {
#pragma unroll
        for (int i = 0; i < 2; i++) {
            int idx = tid + 256 * i;
            int r = idx >> 2, q = (idx & 3) * 4;
            *(float4*)&As[r][q] = *(const float4*)&x[(size_t)(m0 + r) * INPUT + k0 + q];
            *(float4*)&Bs[r][q] = *(const float4*)&Wih[(size_t)(n0 + r) * INPUT + k0 + q];
        }
        __syncthreads();
#pragma unroll
        for (int kk = 0; kk < 16; kk += 8) {
            uint32_t a[2][4], b[8][2];
#pragma unroll
            for (int mt = 0; mt < 2; mt++) {
                int r = wm * 32 + mt * 16 + lr;
                a[mt][0] = f2tf(As[r][kk + lc]);
                a[mt][1] = f2tf(As[r + 8][kk + lc]);
                a[mt][2] = f2tf(As[r][kk + lc + 4]);
                a[mt][3] = f2tf(As[r + 8][kk + lc + 4]);
            }
#pragma unroll
            for (int nt = 0; nt < 8; nt++) {
                int n = wn * 64 + nt * 8 + lr;
                b[nt][0] = f2tf(Bs[n][kk + lc]);
                b[nt][1] = f2tf(Bs[n][kk + lc + 4]);
            }
#pragma unroll
            for (int mt = 0; mt < 2; mt++)
#pragma unroll
                for (int nt = 0; nt < 8; nt++)
                    mma_tf32(acc[mt][nt], a[mt], b[nt]);
        }
        __syncthreads();
    }

    // epilogue: add biases, scatter to [t][b][n]
#pragma unroll
    for (int nt = 0; nt < 8; nt++) {
        int col = n0 + wn * 64 + nt * 8 + 2 * lc;
        float bias0 = bih[col] + bhh[col];
        float bias1 = bih[col + 1] + bhh[col + 1];
#pragma unroll
        for (int mt = 0; mt < 2; mt++) {
            int r0 = m0 + wm * 32 + mt * 16 + lr;
            int r1 = r0 + 8;
            size_t o0 = ((size_t)(r0 & (SEQ - 1)) * BATCH + (r0 >> 9)) * G4 + col;
            size_t o1 = ((size_t)(r1 & (SEQ - 1)) * BATCH + (r1 >> 9)) * G4 + col;
            g_xproj[o0]     = acc[mt][nt][0] + bias0;
            g_xproj[o0 + 1] = acc[mt][nt][1] + bias1;
            g_xproj[o1]     = acc[mt][nt][2] + bias0;
            g_xproj[o1 + 1] = acc[mt][nt][3] + bias1;
        }
    }
}

// ---------------- phase 2: one LSTM timestep (bf16 recurrent GEMM) ----------------
// Grid: (HID/16 = 32 hidden slices, BATCH/64 = 4 batch groups) = 128 CTAs, 1 wave.
// Per CTA: gates[64 batch rows][4 gates x 16 units] = h[64,512] @ Whh_slice[64,512]^T
#define HS_LD 520                                   // 512 + 8 bf16 pad (16B aligned rows)
#define GS_LD 68
#define SMEM_STEP (2 * 64 * HS_LD * 2 + 64 * GS_LD * 4)   // 150528 bytes

__global__ __launch_bounds__(256) void lstm_step_kernel(int t) {
    extern __shared__ char smraw[];
    __nv_bfloat16* hs = (__nv_bfloat16*)smraw;      // [64][HS_LD] h group
    __nv_bfloat16* ws = hs + 64 * HS_LD;            // [64][HS_LD] W_hh slice (rows: gate*16+unit)
    float* gs = (float*)(ws + 64 * HS_LD);          // [64][GS_LD] gate accumulators

    const int j0 = blockIdx.x * 16;                 // hidden-unit slice
    const int b0 = blockIdx.y * 64;                 // batch group
    const int tid = threadIdx.x;
    const int w = tid >> 5, l = tid & 31;
    const int wm = w >> 2, wn = w & 3;              // 2x4 warp grid, warp tile 32x16
    const int lr = l >> 2, lc2 = (l & 3) * 2;

    const __nv_bfloat16* hsrc = g_hbuf[t & 1] + (size_t)b0 * HID;
#pragma unroll
    for (int i = 0; i < 16; i++) {                  // 4096 float4 copies over 256 threads
        int idx = tid + 256 * i;
        int r = idx >> 6, q = (idx & 63) * 8;
        *(float4*)&hs[r * HS_LD + q] = *(const float4*)&hsrc[r * HID + q];
        int gi = r >> 4, u = r & 15;
        const __nv_bfloat16* wsrc = g_Whh_bf + (size_t)(gi * HID + j0 + u) * HID;
        *(float4*)&ws[r * HS_LD + q] = *(const float4*)&wsrc[q];
    }
    __syncthreads();

    float acc[2][2][4] = {};
#pragma unroll 2
    for (int k0 = 0; k0 < 32; k0++) {               // K = 512, k16 steps
        int kb = k0 * 16;
        uint32_t a[2][4], b[2][2];
#pragma unroll
        for (int mt = 0; mt < 2; mt++) {
            int r = wm * 32 + mt * 16 + lr;
            const __nv_bfloat16* p = hs + r * HS_LD + kb + lc2;
            a[mt][0] = *(const uint32_t*)p;
            a[mt][1] = *(const uint32_t*)(p + 8 * HS_LD);
            a[mt][2] = *(const uint32_t*)(p + 8);
            a[mt][3] = *(const uint32_t*)(p + 8 * HS_LD + 8);
        }
#pragma unroll
        for (int nt = 0; nt < 2; nt++) {
            int n = wn * 16 + nt * 8 + lr;
            const __nv_bfloat16* p = ws + n * HS_LD + kb + lc2;
            b[nt][0] = *(const uint32_t*)p;
            b[nt][1] = *(const uint32_t*)(p + 8);
        }
#pragma unroll
        for (int mt = 0; mt < 2; mt++)
#pragma unroll
            for (int nt = 0; nt < 2; nt++)
                mma_bf16(acc[mt][nt], a[mt], b[nt]);
    }

#pragma unroll
    for (int mt = 0; mt < 2; mt++) {
        int row = wm * 32 + mt * 16 + lr;
#pragma unroll
        for (int nt = 0; nt < 2; nt++) {
            int col = wn * 16 + nt * 8 + lc2;
            *(float2*)&gs[row * GS_LD + col]       = make_float2(acc[mt][nt][0], acc[mt][nt][1]);
            *(float2*)&gs[(row + 8) * GS_LD + col] = make_float2(acc[mt][nt][2], acc[mt][nt][3]);
        }
    }
    __syncthreads();

    // epilogue: gates -> (c, h)
    const float* xp = g_xproj + (size_t)t * BATCH * G4;
    __nv_bfloat16* hdst = g_hbuf[(t + 1) & 1];
    for (int i = tid; i < 64 * 16; i += 256) {
        int u = i & 15, bb = i >> 4;
        int gb = b0 + bb, gj = j0 + u;
        const float* xr = xp + (size_t)gb * G4 + gj;
        float pi = gs[bb * GS_LD + u]      + xr[0];
        float pf = gs[bb * GS_LD + 16 + u] + xr[HID];
        float pg = gs[bb * GS_LD + 32 + u] + xr[2 * HID];
        float po = gs[bb * GS_LD + 48 + u] + xr[3 * HID];
        float ig = 1.f / (1.f + __expf(-pi));
        float fg = 1.f / (1.f + __expf(-pf));
        float gg = tanhf(pg);
        float og = 1.f / (1.f + __expf(-po));
        float c = fg * g_c[gb * HID + gj] + ig * gg;
        g_c[gb * HID + gj] = c;
        float h = og * tanhf(c);
        hdst[gb * HID + gj] = __float2bfloat16(h);
        if (t == SEQ - 1) g_hlast[gb * HID + gj] = h;
    }
}

// ---------------- phase 3: FC head (fp32) ----------------
__global__ __launch_bounds__(128) void fc_kernel(const float* __restrict__ Wfc,
                                                 const float* __restrict__ bfc,
                                                 float* __restrict__ out) {
    __shared__ float hrow[HID];
    int b = blockIdx.x, tid = threadIdx.x;
    for (int i = tid; i < HID; i += 128) hrow[i] = g_hlast[b * HID + i];
    __syncthreads();
    float acc = bfc[tid];
    const float4* wr = (const float4*)(Wfc + (size_t)tid * HID);
#pragma unroll 8
    for (int k = 0; k < HID / 4; k++) {
        float4 wv = wr[k];
        const float* hv = &hrow[k * 4];
        acc += hv[0] * wv.x + hv[1] * wv.y + hv[2] * wv.z + hv[3] * wv.w;
    }
    out[b * NCLS + tid] = acc;
}

// ---------------- launch ----------------
extern "C" void kernel_launch(void* const* d_in, const int* in_sizes, int n_in,
                              void* d_out, int out_size) {
    const float* x   = (const float*)d_in[0];
    const float* Wih = (const float*)d_in[1];
    const float* Whh = (const float*)d_in[2];
    const float* bih = (const float*)d_in[3];
    const float* bhh = (const float*)d_in[4];
    const float* Wfc = (const float*)d_in[5];
    const float* bfc = (const float*)d_in[6];
    float* out = (float*)d_out;

    cudaFuncSetAttribute(lstm_step_kernel, cudaFuncAttributeMaxDynamicSharedMemorySize, SMEM_STEP);

    setup_kernel<<<1024, 256>>>(Whh);

    dim3 gx(G4 / 128, (BATCH * SEQ) / 128);         // (16, 1024)
    xproj_kernel<<<gx, 256>>>(x, Wih, bih, bhh);

    for (int t = 0; t < SEQ; t++)
        lstm_step_kernel<<<dim3(HID / 16, BATCH / 64), 256, SMEM_STEP>>>(t);

    fc_kernel<<<BATCH, 128>>>(Wfc, bfc, out);
}

// round 2
// speedup vs baseline: 1.1629x; 1.1629x over previous
#include <cuda_runtime.h>
#include <cuda_bf16.h>
#include <cstdint>

#define INPUT 256
#define HID   512
#define G4    2048
#define BATCH 256
#define SEQ   512
#define NCLS  128
#define NCTA  128

// ---------------- static scratch (no allocation allowed) ----------------
__device__ float          g_xproj[SEQ * BATCH * G4];   // 1 GiB: [t][b][4H] preactivations (biases folded)
__device__ __nv_bfloat16  g_Whh_bf[G4 * HID];          // bf16 copy of W_hh
__device__ __nv_bfloat16  g_hbuf[2][BATCH * HID];      // double-buffered hidden state (bf16)
__device__ float          g_hlast[BATCH * HID];        // final h in fp32 for the FC
__device__ volatile unsigned g_flags[NCTA];            // grid barrier: per-CTA generation flags

// ---------------- mma helpers ----------------
__device__ __forceinline__ uint32_t f2tf(float f) {
    uint32_t r;
    asm("cvt.rna.tf32.f32 %0, %1;" : "=r"(r) : "f"(f));
    return r;
}

__device__ __forceinline__ void mma_tf32(float c[4], const uint32_t a[4], const uint32_t b[2]) {
    asm volatile(
        "mma.sync.aligned.m16n8k8.row.col.f32.tf32.tf32.f32 "
        "{%0,%1,%2,%3}, {%4,%5,%6,%7}, {%8,%9}, {%0,%1,%2,%3};\n"
        : "+f"(c[0]), "+f"(c[1]), "+f"(c[2]), "+f"(c[3])
        : "r"(a[0]), "r"(a[1]), "r"(a[2]), "r"(a[3]), "r"(b[0]), "r"(b[1]));
}

__device__ __forceinline__ void mma_bf16(float c[4], const uint32_t a[4], const uint32_t b[2]) {
    asm volatile(
        "mma.sync.aligned.m16n8k16.row.col.f32.bf16.bf16.f32 "
        "{%0,%1,%2,%3}, {%4,%5,%6,%7}, {%8,%9}, {%0,%1,%2,%3};\n"
        : "+f"(c[0]), "+f"(c[1]), "+f"(c[2]), "+f"(c[3])
        : "r"(a[0]), "r"(a[1]), "r"(a[2]), "r"(a[3]), "r"(b[0]), "r"(b[1]));
}

// ---------------- setup: convert W_hh to bf16, zero h0, reset barrier ----------------
__global__ void setup_kernel(const float* __restrict__ Whh) {
    int stride = gridDim.x * blockDim.x;
    int tid0 = blockIdx.x * blockDim.x + threadIdx.x;
    for (int i = tid0; i < G4 * HID; i += stride)
        g_Whh_bf[i] = __float2bfloat16(Whh[i]);
    for (int i = tid0; i < BATCH * HID; i += stride)
        g_hbuf[0][i] = __float2bfloat16(0.f);
    if (tid0 < NCTA) ((unsigned*)g_flags)[tid0] = 0u;
}

// ---------------- phase 1: x_proj GEMM (tf32) ----------------
// C[m, n] = sum_k x[m, k] * W_ih[n, k] + (b_ih[n] + b_hh[n]),  m = b*SEQ + t
// Output stored as g_xproj[t][b][n].
__global__ __launch_bounds__(256) void xproj_kernel(
    const float* __restrict__ x, const float* __restrict__ Wih,
    const float* __restrict__ bih, const float* __restrict__ bhh) {
    __shared__ float As[128][20];   // pad 20 -> conflict-free frag loads
    __shared__ float Bs[128][20];

    const int m0 = blockIdx.y * 128;
    const int n0 = blockIdx.x * 128;
    const int tid = threadIdx.x;
    const int w = tid >> 5, l = tid & 31;
    const int wm = w >> 1, wn = w & 1;       // 4x2 warp grid, warp tile 32x64
    const int lr = l >> 2, lc = l & 3;

    float acc[2][8][4] = {};

    for (int k0 = 0; k0 < INPUT; k0 += 16) {
#pragma unroll
        for (int i = 0; i < 2; i++) {
            int idx = tid + 256 * i;
            int r = idx >> 2, q = (idx & 3) * 4;
            *(float4*)&As[r][q] = *(const float4*)&x[(size_t)(m0 + r) * INPUT + k0 + q];
            *(float4*)&Bs[r][q] = *(const float4*)&Wih[(size_t)(n0 + r) * INPUT + k0 + q];
        }
        __syncthreads();
#pragma unroll
        for (int kk = 0; kk < 16; kk += 8) {
            uint32_t a[2][4], b[8][2];
#pragma unroll
            for (int mt = 0; mt < 2; mt++) {
                int r = wm * 32 + mt * 16 + lr;
                a[mt][0] = f2tf(As[r][kk + lc]);
                a[mt][1] = f2tf(As[r + 8][kk + lc]);
                a[mt][2] = f2tf(As[r][kk + lc + 4]);
                a[mt][3] = f2tf(As[r + 8][kk + lc + 4]);
            }
#pragma unroll
            for (int nt = 0; nt < 8; nt++) {
                int n = wn * 64 + nt * 8 + lr;
                b[nt][0] = f2tf(Bs[n][kk + lc]);
                b[nt][1] = f2tf(Bs[n][kk + lc + 4]);
            }
#pragma unroll
            for (int mt = 0; mt < 2; mt++)
#pragma unroll
                for (int nt = 0; nt < 8; nt++)
                    mma_tf32(acc[mt][nt], a[mt], b[nt]);
        }
        __syncthreads();
    }

    // epilogue: add biases, scatter to [t][b][n]
#pragma unroll
    for (int nt = 0; nt < 8; nt++) {
        int col = n0 + wn * 64 + nt * 8 + 2 * lc;
        float bias0 = bih[col] + bhh[col];
        float bias1 = bih[col + 1] + bhh[col + 1];
#pragma unroll
        for (int mt = 0; mt < 2; mt++) {
            int r0 = m0 + wm * 32 + mt * 16 + lr;
            int r1 = r0 + 8;
            size_t o0 = ((size_t)(r0 & (SEQ - 1)) * BATCH + (r0 >> 9)) * G4 + col;
            size_t o1 = ((size_t)(r1 & (SEQ - 1)) * BATCH + (r1 >> 9)) * G4 + col;
            g_xproj[o0]     = acc[mt][nt][0] + bias0;
            g_xproj[o0 + 1] = acc[mt][nt][1] + bias1;
            g_xproj[o1]     = acc[mt][nt][2] + bias0;
            g_xproj[o1 + 1] = acc[mt][nt][3] + bias1;
        }
    }
}

// ---------------- phase 2: persistent LSTM scan ----------------
// Grid: (32 hidden slices, 4 batch groups) = 128 CTAs, all co-resident (1 CTA/SM).
// Per CTA per step: gates[64 batch rows][4 gates x 16 units] = h[64,512] @ Whh_slice[64,512]^T
// W_hh slice resides in smem for the whole scan; c lives in registers.
#define HS_LD 520                                   // 512 + 8 bf16 pad (16B aligned rows)
#define GS_LD 68
#define SMEM_STEP (2 * 64 * HS_LD * 2 + 64 * GS_LD * 4)   // 150528 bytes

__global__ __launch_bounds__(256) void lstm_scan_kernel() {
    extern __shared__ char smraw[];
    __nv_bfloat16* hs = (__nv_bfloat16*)smraw;      // [64][HS_LD] h group (refilled each step)
    __nv_bfloat16* ws = hs + 64 * HS_LD;            // [64][HS_LD] W_hh slice (persistent)
    float* gs = (float*)(ws + 64 * HS_LD);          // [64][GS_LD] gate accumulators

    const int j0 = blockIdx.x * 16;                 // hidden-unit slice
    const int b0 = blockIdx.y * 64;                 // batch group
    const int bid = blockIdx.y * 32 + blockIdx.x;
    const int tid = threadIdx.x;
    const int w = tid >> 5, l = tid & 31;
    const int wm = w >> 2, wn = w & 3;              // 2x4 warp grid, warp tile 32x16
    const int lr = l >> 2, lc2 = (l & 3) * 2;
    const int u = tid & 15;                          // epilogue unit (const across e)
    const int bbb = tid >> 4;                        // epilogue batch base (bb = bbb + 16e)

    // ---- load W_hh slice once (rows: gate*16 + unit) ----
#pragma unroll
    for (int i = 0; i < 16; i++) {
        int idx = tid + 256 * i;
        int r = idx >> 6, q = (idx & 63) * 8;
        int gi = r >> 4, uu = r & 15;
        *(float4*)&ws[r * HS_LD + q] =
            *(const float4*)&g_Whh_bf[(size_t)(gi * HID + j0 + uu) * HID + q];
    }

    float c_reg[4] = {0.f, 0.f, 0.f, 0.f};          // cell state, register-resident all 512 steps

    for (int t = 0; t < SEQ; t++) {
        // ---- prefetch x_proj for this step's epilogue (hidden behind h-fill + MMA) ----
        const float* xp = g_xproj + (size_t)t * BATCH * G4;
        float xi[4], xf[4], xg[4], xo[4];
#pragma unroll
        for (int e = 0; e < 4; e++) {
            const float* xr = xp + (size_t)(b0 + bbb + 16 * e) * G4 + (j0 + u);
            xi[e] = xr[0];
            xf[e] = xr[HID];
            xg[e] = xr[2 * HID];
            xo[e] = xr[3 * HID];
        }

        // ---- fill h group (64 KB from L2) ----
        const __nv_bfloat16* hsrc = g_hbuf[t & 1] + (size_t)b0 * HID;
#pragma unroll
        for (int i = 0; i < 16; i++) {
            int idx = tid + 256 * i;
            int r = idx >> 6, q = (idx & 63) * 8;
            *(float4*)&hs[r * HS_LD + q] = *(const float4*)&hsrc[r * HID + q];
        }
        __syncthreads();

        // ---- 64x64x512 bf16 MMA ----
        float acc[2][2][4] = {};
#pragma unroll 2
        for (int k0 = 0; k0 < 32; k0++) {
            int kb = k0 * 16;
            uint32_t a[2][4], b[2][2];
#pragma unroll
            for (int mt = 0; mt < 2; mt++) {
                int r = wm * 32 + mt * 16 + lr;
                const __nv_bfloat16* p = hs + r * HS_LD + kb + lc2;
                a[mt][0] = *(const uint32_t*)p;
                a[mt][1] = *(const uint32_t*)(p + 8 * HS_LD);
                a[mt][2] = *(const uint32_t*)(p + 8);
                a[mt][3] = *(const uint32_t*)(p + 8 * HS_LD + 8);
            }
#pragma unroll
            for (int nt = 0; nt < 2; nt++) {
                int n = wn * 16 + nt * 8 + lr;
                const __nv_bfloat16* p = ws + n * HS_LD + kb + lc2;
                b[nt][0] = *(const uint32_t*)p;
                b[nt][1] = *(const uint32_t*)(p + 8);
            }
#pragma unroll
            for (int mt = 0; mt < 2; mt++)
#pragma unroll
                for (int nt = 0; nt < 2; nt++)
                    mma_bf16(acc[mt][nt], a[mt], b[nt]);
        }

#pragma unroll
        for (int mt = 0; mt < 2; mt++) {
            int row = wm * 32 + mt * 16 + lr;
#pragma unroll
            for (int nt = 0; nt < 2; nt++) {
                int col = wn * 16 + nt * 8 + lc2;
                *(float2*)&gs[row * GS_LD + col]       = make_float2(acc[mt][nt][0], acc[mt][nt][1]);
                *(float2*)&gs[(row + 8) * GS_LD + col] = make_float2(acc[mt][nt][2], acc[mt][nt][3]);
            }
        }
        __syncthreads();

        // ---- epilogue: gates -> (c, h) ----
        __nv_bfloat16* hdst = g_hbuf[(t + 1) & 1];
#pragma unroll
        for (int e = 0; e < 4; e++) {
            int bb = bbb + 16 * e;
            float pi = gs[bb * GS_LD + u]      + xi[e];
            float pf = gs[bb * GS_LD + 16 + u] + xf[e];
            float pg = gs[bb * GS_LD + 32 + u] + xg[e];
            float po = gs[bb * GS_LD + 48 + u] + xo[e];
            float ig = 1.f / (1.f + __expf(-pi));
            float fg = 1.f / (1.f + __expf(-pf));
            float gg = tanhf(pg);
            float og = 1.f / (1.f + __expf(-po));
            float c = fg * c_reg[e] + ig * gg;
            c_reg[e] = c;
            float h = og * tanhf(c);
            size_t oidx = (size_t)(b0 + bb) * HID + (j0 + u);
            if (t == SEQ - 1) {
                g_hlast[oidx] = h;
            } else {
                hdst[oidx] = __float2bfloat16(h);
            }
        }

        // ---- grid barrier (flag-array, release/acquire) ----
        if (t != SEQ - 1) {
            __syncthreads();                        // all epilogue stores issued
            if (tid == 0) {
                __threadfence();                    // release this CTA's h writes
                g_flags[bid] = (unsigned)(t + 1);
            }
            if (tid < NCTA) {
                while (g_flags[tid] < (unsigned)(t + 1)) { }
                __threadfence();                    // acquire observed CTAs' h writes
            }
            __syncthreads();
        }
    }
}

// ---------------- phase 3: FC head (fp32) ----------------
__global__ __launch_bounds__(128) void fc_kernel(const float* __restrict__ Wfc,
                                                 const float* __restrict__ bfc,
                                                 float* __restrict__ out) {
    __shared__ float hrow[HID];
    int b = blockIdx.x, tid = threadIdx.x;
    for (int i = tid; i < HID; i += 128) hrow[i] = g_hlast[b * HID + i];
    __syncthreads();
    float acc = bfc[tid];
    const float4* wr = (const float4*)(Wfc + (size_t)tid * HID);
#pragma unroll 8
    for (int k = 0; k < HID / 4; k++) {
        float4 wv = wr[k];
        const float* hv = &hrow[k * 4];
        acc += hv[0] * wv.x + hv[1] * wv.y + hv[2] * wv.z + hv[3] * wv.w;
    }
    out[b * NCLS + tid] = acc;
}

// ---------------- launch ----------------
extern "C" void kernel_launch(void* const* d_in, const int* in_sizes, int n_in,
                              void* d_out, int out_size) {
    const float* x   = (const float*)d_in[0];
    const float* Wih = (const float*)d_in[1];
    const float* Whh = (const float*)d_in[2];
    const float* bih = (const float*)d_in[3];
    const float* bhh = (const float*)d_in[4];
    const float* Wfc = (const float*)d_in[5];
    const float* bfc = (const float*)d_in[6];
    float* out = (float*)d_out;

    cudaFuncSetAttribute(lstm_scan_kernel, cudaFuncAttributeMaxDynamicSharedMemorySize, SMEM_STEP);

    setup_kernel<<<1024, 256>>>(Whh);

    dim3 gx(G4 / 128, (BATCH * SEQ) / 128);         // (16, 1024)
    xproj_kernel<<<gx, 256>>>(x, Wih, bih, bhh);

    lstm_scan_kernel<<<dim3(HID / 16, BATCH / 64), 256, SMEM_STEP>>>();

    fc_kernel<<<BATCH, 128>>>(Wfc, bfc, out);
}

// round 4
// speedup vs baseline: 1.2198x; 1.0490x over previous
#include <cuda_runtime.h>
#include <cuda_bf16.h>
#include <cstdint>

#define INPUT 256
#define HID   512
#define G4    2048
#define BATCH 256
#define SEQ   512
#define NCLS  128

// ---------------- static scratch (no allocation allowed) ----------------
__device__ float          g_xproj[SEQ * BATCH * G4];   // 1 GiB: [t][b][4H] preactivations (biases folded)
__device__ __nv_bfloat16  g_Whh_bf[G4 * HID];          // bf16 copy of W_hh
__device__ __nv_bfloat16  g_hbuf[2][BATCH * HID];      // double-buffered hidden state (bf16)
__device__ float          g_hlast[BATCH * HID];        // final h in fp32 for the FC
__device__ unsigned       g_flags[4][32];              // per-batch-group barrier flags

// ---------------- asm helpers ----------------
__device__ __forceinline__ uint32_t f2tf(float f) {
    uint32_t r;
    asm("cvt.rna.tf32.f32 %0, %1;" : "=r"(r) : "f"(f));
    return r;
}

__device__ __forceinline__ void mma_tf32(float c[4], const uint32_t a[4], const uint32_t b[2]) {
    asm volatile(
        "mma.sync.aligned.m16n8k8.row.col.f32.tf32.tf32.f32 "
        "{%0,%1,%2,%3}, {%4,%5,%6,%7}, {%8,%9}, {%0,%1,%2,%3};\n"
        : "+f"(c[0]), "+f"(c[1]), "+f"(c[2]), "+f"(c[3])
        : "r"(a[0]), "r"(a[1]), "r"(a[2]), "r"(a[3]), "r"(b[0]), "r"(b[1]));
}

__device__ __forceinline__ void mma_bf16(float c[4], const uint32_t a[4], const uint32_t b[2]) {
    asm volatile(
        "mma.sync.aligned.m16n8k16.row.col.f32.bf16.bf16.f32 "
        "{%0,%1,%2,%3}, {%4,%5,%6,%7}, {%8,%9}, {%0,%1,%2,%3};\n"
        : "+f"(c[0]), "+f"(c[1]), "+f"(c[2]), "+f"(c[3])
        : "r"(a[0]), "r"(a[1]), "r"(a[2]), "r"(a[3]), "r"(b[0]), "r"(b[1]));
}

__device__ __forceinline__ void ldsm_x4(uint32_t& r0, uint32_t& r1, uint32_t& r2, uint32_t& r3,
                                        uint32_t addr) {
    asm volatile("ldmatrix.sync.aligned.m8n8.x4.shared.b16 {%0,%1,%2,%3}, [%4];"
                 : "=r"(r0), "=r"(r1), "=r"(r2), "=r"(r3) : "r"(addr));
}

#define CP_ASYNC16(sm, gp) asm volatile("cp.async.cg.shared.global [%0], [%1], 16;" :: "r"(sm), "l"(gp))
#define CP_COMMIT          asm volatile("cp.async.commit_group;")
#define CP_WAIT1           asm volatile("cp.async.wait_group 1;")
#define CP_WAIT0           asm volatile("cp.async.wait_group 0;")

// fast, nan-safe activations (EX2 + approx RCP, ~1e-6 err)
__device__ __forceinline__ float fsigmoid(float x) {
    return __fdividef(1.f, 1.f + __expf(-x));
}
__device__ __forceinline__ float ftanh(float x) {
    // 2*sigmoid(2x) - 1 : correct limits at +/-inf, no nan
    return __fmaf_rn(2.f, __fdividef(1.f, 1.f + __expf(-2.f * x)), -1.f);
}

// ---------------- setup: convert W_hh to bf16, zero h0, reset barrier ----------------
__global__ void setup_kernel(const float* __restrict__ Whh) {
    int stride = gridDim.x * blockDim.x;
    int tid0 = blockIdx.x * blockDim.x + threadIdx.x;
    for (int i = tid0; i < G4 * HID; i += stride)
        g_Whh_bf[i] = __float2bfloat16(Whh[i]);
    for (int i = tid0; i < BATCH * HID; i += stride)
        g_hbuf[0][i] = __float2bfloat16(0.f);
    if (tid0 < 128) ((unsigned*)g_flags)[tid0] = 0u;
}

// ---------------- phase 1: x_proj GEMM (tf32, 2-stage cp.async pipeline) ----------------
__global__ __launch_bounds__(256) void xproj_kernel(
    const float* __restrict__ x, const float* __restrict__ Wih,
    const float* __restrict__ bih, const float* __restrict__ bhh) {
    __shared__ float As[2][128][20];
    __shared__ float Bs[2][128][20];

    const int m0 = blockIdx.y * 128;
    const int n0 = blockIdx.x * 128;
    const int tid = threadIdx.x;
    const int w = tid >> 5, l = tid & 31;
    const int wm = w >> 1, wn = w & 1;       // 4x2 warp grid, warp tile 32x64
    const int lr = l >> 2, lc = l & 3;

    const uint32_t as_base = (uint32_t)__cvta_generic_to_shared(&As[0][0][0]);
    const uint32_t bs_base = (uint32_t)__cvta_generic_to_shared(&Bs[0][0][0]);
    const int ld_r = (tid >> 2);                 // rows 0..63 (+64 second half)
    const int ld_q = (tid & 3) * 4;

    float acc[2][8][4] = {};

    // prologue: stage 0
#pragma unroll
    for (int i = 0; i < 2; i++) {
        int r = ld_r + 64 * i;
        CP_ASYNC16(as_base + (uint32_t)((r * 20 + ld_q) * 4),
                   &x[(size_t)(m0 + r) * INPUT + ld_q]);
        CP_ASYNC16(bs_base + (uint32_t)((r * 20 + ld_q) * 4),
                   &Wih[(size_t)(n0 + r) * INPUT + ld_q]);
    }
    CP_COMMIT;

    for (int ks = 0; ks < 16; ks++) {
        const int s = ks & 1;
        if (ks + 1 < 16) {
            const int s2 = (ks + 1) & 1;
            const int k0 = (ks + 1) * 16;
#pragma unroll
            for (int i = 0; i < 2; i++) {
                int r = ld_r + 64 * i;
                CP_ASYNC16(as_base + (uint32_t)(((s2 * 128 + r) * 20 + ld_q) * 4),
                           &x[(size_t)(m0 + r) * INPUT + k0 + ld_q]);
                CP_ASYNC16(bs_base + (uint32_t)(((s2 * 128 + r) * 20 + ld_q) * 4),
                           &Wih[(size_t)(n0 + r) * INPUT + k0 + ld_q]);
            }
            CP_COMMIT;
            CP_WAIT1;
        } else {
            CP_WAIT0;
        }
        __syncthreads();

#pragma unroll
        for (int kk = 0; kk < 16; kk += 8) {
            uint32_t a[2][4], b[8][2];
#pragma unroll
            for (int mt = 0; mt < 2; mt++) {
                int r = wm * 32 + mt * 16 + lr;
                a[mt][0] = f2tf(As[s][r][kk + lc]);
                a[mt][1] = f2tf(As[s][r + 8][kk + lc]);
                a[mt][2] = f2tf(As[s][r][kk + lc + 4]);
                a[mt][3] = f2tf(As[s][r + 8][kk + lc + 4]);
            }
#pragma unroll
            for (int nt = 0; nt < 8; nt++) {
                int n = wn * 64 + nt * 8 + lr;
                b[nt][0] = f2tf(Bs[s][n][kk + lc]);
                b[nt][1] = f2tf(Bs[s][n][kk + lc + 4]);
            }
#pragma unroll
            for (int mt = 0; mt < 2; mt++)
#pragma unroll
                for (int nt = 0; nt < 8; nt++)
                    mma_tf32(acc[mt][nt], a[mt], b[nt]);
        }
        __syncthreads();
    }

    // epilogue: add biases, scatter to [t][b][n]
#pragma unroll
    for (int nt = 0; nt < 8; nt++) {
        int col = n0 + wn * 64 + nt * 8 + 2 * lc;
        float bias0 = bih[col] + bhh[col];
        float bias1 = bih[col + 1] + bhh[col + 1];
#pragma unroll
        for (int mt = 0; mt < 2; mt++) {
            int r0 = m0 + wm * 32 + mt * 16 + lr;
            int r1 = r0 + 8;
            size_t o0 = ((size_t)(r0 & (SEQ - 1)) * BATCH + (r0 >> 9)) * G4 + col;
            size_t o1 = ((size_t)(r1 & (SEQ - 1)) * BATCH + (r1 >> 9)) * G4 + col;
            g_xproj[o0]     = acc[mt][nt][0] + bias0;
            g_xproj[o0 + 1] = acc[mt][nt][1] + bias1;
            g_xproj[o1]     = acc[mt][nt][2] + bias0;
            g_xproj[o1 + 1] = acc[mt][nt][3] + bias1;
        }
    }
}

// ---------------- phase 2: persistent LSTM scan ----------------
// Grid (32 hidden slices, 4 batch groups) = 128 CTAs, 1/SM. Per CTA per step:
// gates[64 batch][4 gates x 16 units] = h[64,512] @ Whh_slice[64,512]^T (bf16 MMA via ldmatrix).
// W_hh slice persists in smem; c register-resident; per-batch-group grid barrier.
#define HS_LD 520                                   // 512 + 8 bf16 pad
#define GS_LD 68
#define SMEM_STEP (2 * 64 * HS_LD * 2 + 64 * GS_LD * 4)   // 150528 bytes

__global__ __launch_bounds__(256) void lstm_scan_kernel() {
    extern __shared__ char smraw[];
    __nv_bfloat16* hs = (__nv_bfloat16*)smraw;      // [64][HS_LD] h group (refilled each step)
    __nv_bfloat16* ws = hs + 64 * HS_LD;            // [64][HS_LD] W_hh slice (persistent)
    float* gs = (float*)(ws + 64 * HS_LD);          // [64][GS_LD] gate accumulators

    const int j0 = blockIdx.x * 16;                 // hidden-unit slice
    const int b0 = blockIdx.y * 64;                 // batch group
    const int bx = blockIdx.x, by = blockIdx.y;
    const int tid = threadIdx.x;
    const int w = tid >> 5, l = tid & 31;
    const int wm = w >> 2, wn = w & 3;              // 2x4 warp grid, warp tile 32x16
    const int lr = l >> 2, lc2 = (l & 3) * 2;
    const int u = tid & 15;                          // epilogue unit
    const int bbb = tid >> 4;                        // epilogue batch base (bb = bbb + 16e)

    // ---- load W_hh slice once (rows: gate*16 + unit) ----
#pragma unroll
    for (int i = 0; i < 16; i++) {
        int idx = tid + 256 * i;
        int r = idx >> 6, q = (idx & 63) * 8;
        int gi = r >> 4, uu = r & 15;
        *(float4*)&ws[r * HS_LD + q] =
            *(const float4*)&g_Whh_bf[(size_t)(gi * HID + j0 + uu) * HID + q];
    }

    // ---- precompute ldmatrix shared addresses ----
    const uint32_t hs_base = (uint32_t)__cvta_generic_to_shared(hs);
    const uint32_t ws_base = (uint32_t)__cvta_generic_to_shared(ws);
    // A: lanes 0-7 M(r0-7,k0-7), 8-15 M(r8-15,k0-7), 16-23 M(r0-7,k8-15), 24-31 M(r8-15,k8-15)
    const uint32_t a_addr0 = hs_base +
        (uint32_t)(((wm * 32 + (l & 15)) * HS_LD + ((l >> 4) * 8)) * 2);
    const uint32_t a_addr1 = a_addr0 + 16 * HS_LD * 2;
    // B x4 over 16 n-rows: M0=(n0-7,k0-7), M1=(n0-7,k8-15), M2=(n8-15,k0-7), M3=(n8-15,k8-15)
    const uint32_t b_addr = ws_base +
        (uint32_t)(((wn * 16 + (l & 7) + ((l >> 4) << 3)) * HS_LD + (((l >> 3) & 1) * 8)) * 2);

    float c_reg[4] = {0.f, 0.f, 0.f, 0.f};

    for (int t = 0; t < SEQ; t++) {
        // ---- prefetch x_proj for this step's epilogue ----
        const float* xp = g_xproj + (size_t)t * BATCH * G4;
        float xi[4], xf[4], xg[4], xo[4];
#pragma unroll
        for (int e = 0; e < 4; e++) {
            const float* xr = xp + (size_t)(b0 + bbb + 16 * e) * G4 + (j0 + u);
            xi[e] = xr[0];
            xf[e] = xr[HID];
            xg[e] = xr[2 * HID];
            xo[e] = xr[3 * HID];
        }

        // ---- fill h group (64 KB from L2) ----
        const __nv_bfloat16* hsrc = g_hbuf[t & 1] + (size_t)b0 * HID;
#pragma unroll
        for (int i = 0; i < 16; i++) {
            int idx = tid + 256 * i;
            int r = idx >> 6, q = (idx & 63) * 8;
            *(float4*)&hs[r * HS_LD + q] = *(const float4*)&hsrc[r * HID + q];
        }
        __syncthreads();

        // ---- 64x64x512 bf16 MMA (ldmatrix fragments) ----
        float acc[2][2][4] = {};
#pragma unroll 4
        for (int k0 = 0; k0 < 32; k0++) {
            const uint32_t kofs = (uint32_t)(k0 * 32);   // 16 bf16 = 32 bytes
            uint32_t a[2][4], b[2][2];
            ldsm_x4(a[0][0], a[0][1], a[0][2], a[0][3], a_addr0 + kofs);
            ldsm_x4(a[1][0], a[1][1], a[1][2], a[1][3], a_addr1 + kofs);
            ldsm_x4(b[0][0], b[0][1], b[1][0], b[1][1], b_addr + kofs);
#pragma unroll
            for (int mt = 0; mt < 2; mt++)
#pragma unroll
                for (int nt = 0; nt < 2; nt++)
                    mma_bf16(acc[mt][nt], a[mt], b[nt]);
        }

#pragma unroll
        for (int mt = 0; mt < 2; mt++) {
            int row = wm * 32 + mt * 16 + lr;
#pragma unroll
            for (int nt = 0; nt < 2; nt++) {
                int col = wn * 16 + nt * 8 + lc2;
                *(float2*)&gs[row * GS_LD + col]       = make_float2(acc[mt][nt][0], acc[mt][nt][1]);
                *(float2*)&gs[(row + 8) * GS_LD + col] = make_float2(acc[mt][nt][2], acc[mt][nt][3]);
            }
        }
        __syncthreads();

        // ---- epilogue: gates -> (c, h) ----
        __nv_bfloat16* hdst = g_hbuf[(t + 1) & 1];
#pragma unroll
        for (int e = 0; e < 4; e++) {
            int bb = bbb + 16 * e;
            float pi = gs[bb * GS_LD + u]      + xi[e];
            float pf = gs[bb * GS_LD + 16 + u] + xf[e];
            float pg = gs[bb * GS_LD + 32 + u] + xg[e];
            float po = gs[bb * GS_LD + 48 + u] + xo[e];
            float ig = fsigmoid(pi);
            float fg = fsigmoid(pf);
            float gg = ftanh(pg);
            float og = fsigmoid(po);
            float c = fg * c_reg[e] + ig * gg;
            c_reg[e] = c;
            float h = og * ftanh(c);
            size_t oidx = (size_t)(b0 + bb) * HID + (j0 + u);
            if (t == SEQ - 1) {
                g_hlast[oidx] = h;
            } else {
                hdst[oidx] = __float2bfloat16(h);
            }
        }

        // ---- per-batch-group barrier (32 CTAs, release/acquire flags) ----
        if (t != SEQ - 1) {
            __syncthreads();                        // all epilogue stores issued
            if (tid == 0) {
                asm volatile("st.release.gpu.global.u32 [%0], %1;"
                             :: "l"(&g_flags[by][bx]), "r"((unsigned)(t + 1)) : "memory");
            }
            if (tid < 32) {
                unsigned v;
                do {
                    asm volatile("ld.acquire.gpu.global.u32 %0, [%1];"
                                 : "=r"(v) : "l"(&g_flags[by][tid]) : "memory");
                } while (v < (unsigned)(t + 1));
            }
            __syncthreads();
        }
    }
}

// ---------------- phase 3: FC head (fp32, tiled, dynamic-smem staged) ----------------
// grid (NCLS/16, BATCH/16) = (8,16), block 256: thread -> (class, batch) cell.
#define FC_LD 516
#define SMEM_FC (2 * 16 * FC_LD * 4)                // 66048 bytes (dynamic, opt-in)
__global__ __launch_bounds__(256) void fc_kernel(const float* __restrict__ Wfc,
                                                 const float* __restrict__ bfc,
                                                 float* __restrict__ out) {
    extern __shared__ float fcsm[];
    float* hsm = fcsm;                              // [16][FC_LD]
    float* wsm = fcsm + 16 * FC_LD;                 // [16][FC_LD]
    const int cg = blockIdx.x * 16, bg = blockIdx.y * 16;
    const int tid = threadIdx.x;

    // stage: 16 rows x 512 floats each, coalesced (32 floats = 8 float4 per thread)
    {
        int r = tid >> 4, q = (tid & 15) * 4;       // q: 0..60 step 4
#pragma unroll
        for (int i = 0; i < 8; i++) {
            *(float4*)&hsm[r * FC_LD + q + 64 * i] =
                *(const float4*)&g_hlast[(size_t)(bg + r) * HID + q + 64 * i];
            *(float4*)&wsm[r * FC_LD + q + 64 * i] =
                *(const float4*)&Wfc[(size_t)(cg + r) * HID + q + 64 * i];
        }
    }
    __syncthreads();

    const int c = tid & 15, b = tid >> 4;
    float acc = bfc[cg + c];
#pragma unroll 8
    for (int k = 0; k < HID; k += 4) {
        float4 wv = *(float4*)&wsm[c * FC_LD + k];
        float4 hv = *(float4*)&hsm[b * FC_LD + k];
        acc += hv.x * wv.x + hv.y * wv.y + hv.z * wv.z + hv.w * wv.w;
    }
    out[(size_t)(bg + b) * NCLS + cg + c] = acc;
}

// ---------------- launch ----------------
extern "C" void kernel_launch(void* const* d_in, const int* in_sizes, int n_in,
                              void* d_out, int out_size) {
    const float* x   = (const float*)d_in[0];
    const float* Wih = (const float*)d_in[1];
    const float* Whh = (const float*)d_in[2];
    const float* bih = (const float*)d_in[3];
    const float* bhh = (const float*)d_in[4];
    const float* Wfc = (const float*)d_in[5];
    const float* bfc = (const float*)d_in[6];
    float* out = (float*)d_out;

    cudaFuncSetAttribute(lstm_scan_kernel, cudaFuncAttributeMaxDynamicSharedMemorySize, SMEM_STEP);
    cudaFuncSetAttribute(fc_kernel, cudaFuncAttributeMaxDynamicSharedMemorySize, SMEM_FC);

    setup_kernel<<<1024, 256>>>(Whh);

    dim3 gx(G4 / 128, (BATCH * SEQ) / 128);         // (16, 1024)
    xproj_kernel<<<gx, 256>>>(x, Wih, bih, bhh);

    lstm_scan_kernel<<<dim3(HID / 16, BATCH / 64), 256, SMEM_STEP>>>();

    fc_kernel<<<dim3(NCLS / 16, BATCH / 16), 256, SMEM_FC>>>(Wfc, bfc, out);
}

// round 5
// speedup vs baseline: 1.2934x; 1.0603x over previous
#include <cuda_runtime.h>
#include <cuda_bf16.h>
#include <cstdint>

#define INPUT 256
#define HID   512
#define G4    2048
#define BATCH 256
#define SEQ   512
#define NCLS  128

// scan geometry: 16 j-slices x 4 batch-groups = 64 CTAs
#define NJ    16
#define NB    4
#define JW    32          // hidden units per CTA
#define BW    64          // batch rows per CTA

// ---------------- static scratch (no allocation allowed) ----------------
__device__ float          g_xproj[SEQ * BATCH * G4];   // [t][b][4H] preactivations (biases folded)
__device__ __nv_bfloat16  g_Whh_bf[G4 * HID];          // bf16 copy of W_hh
__device__ __nv_bfloat16  g_hbuf[2][BATCH * HID];      // double-buffered hidden state (bf16)
__device__ float          g_hlast[BATCH * HID];        // final h in fp32 for the FC
__device__ unsigned       g_flags[NB][NJ];             // per-batch-group barrier flags

// ---------------- asm helpers ----------------
__device__ __forceinline__ uint32_t f2tf(float f) {
    uint32_t r;
    asm("cvt.rna.tf32.f32 %0, %1;" : "=r"(r) : "f"(f));
    return r;
}

__device__ __forceinline__ void mma_tf32(float c[4], const uint32_t a[4], const uint32_t b[2]) {
    asm volatile(
        "mma.sync.aligned.m16n8k8.row.col.f32.tf32.tf32.f32 "
        "{%0,%1,%2,%3}, {%4,%5,%6,%7}, {%8,%9}, {%0,%1,%2,%3};\n"
        : "+f"(c[0]), "+f"(c[1]), "+f"(c[2]), "+f"(c[3])
        : "r"(a[0]), "r"(a[1]), "r"(a[2]), "r"(a[3]), "r"(b[0]), "r"(b[1]));
}

__device__ __forceinline__ void mma_bf16(float c[4], const uint32_t a[4], const uint32_t b[2]) {
    asm volatile(
        "mma.sync.aligned.m16n8k16.row.col.f32.bf16.bf16.f32 "
        "{%0,%1,%2,%3}, {%4,%5,%6,%7}, {%8,%9}, {%0,%1,%2,%3};\n"
        : "+f"(c[0]), "+f"(c[1]), "+f"(c[2]), "+f"(c[3])
        : "r"(a[0]), "r"(a[1]), "r"(a[2]), "r"(a[3]), "r"(b[0]), "r"(b[1]));
}

__device__ __forceinline__ void ldsm_x4(uint32_t& r0, uint32_t& r1, uint32_t& r2, uint32_t& r3,
                                        uint32_t addr) {
    asm volatile("ldmatrix.sync.aligned.m8n8.x4.shared.b16 {%0,%1,%2,%3}, [%4];"
                 : "=r"(r0), "=r"(r1), "=r"(r2), "=r"(r3) : "r"(addr));
}

#define CP_ASYNC16(sm, gp) asm volatile("cp.async.cg.shared.global [%0], [%1], 16;" :: "r"(sm), "l"(gp))
#define CP_COMMIT          asm volatile("cp.async.commit_group;")
#define CP_WAIT1           asm volatile("cp.async.wait_group 1;")
#define CP_WAIT0           asm volatile("cp.async.wait_group 0;")

// fast, nan-safe activations
__device__ __forceinline__ float fsigmoid(float x) {
    return __fdividef(1.f, 1.f + __expf(-x));
}
__device__ __forceinline__ float ftanh(float x) {
    return __fmaf_rn(2.f, __fdividef(1.f, 1.f + __expf(-2.f * x)), -1.f);
}

// ---------------- setup ----------------
__global__ void setup_kernel(const float* __restrict__ Whh) {
    int stride = gridDim.x * blockDim.x;
    int tid0 = blockIdx.x * blockDim.x + threadIdx.x;
    for (int i = tid0; i < G4 * HID; i += stride)
        g_Whh_bf[i] = __float2bfloat16(Whh[i]);
    for (int i = tid0; i < BATCH * HID; i += stride)
        g_hbuf[0][i] = __float2bfloat16(0.f);
    if (tid0 < NB * NJ) ((unsigned*)g_flags)[tid0] = 0u;
}

__global__ void dummy_kernel() {}

// ---------------- phase 1: x_proj GEMM (tf32, 2-stage cp.async pipeline) ----------------
__global__ __launch_bounds__(256) void xproj_kernel(
    const float* __restrict__ x, const float* __restrict__ Wih,
    const float* __restrict__ bih, const float* __restrict__ bhh) {
    __shared__ float As[2][128][20];
    __shared__ float Bs[2][128][20];

    const int m0 = blockIdx.y * 128;
    const int n0 = blockIdx.x * 128;
    const int tid = threadIdx.x;
    const int w = tid >> 5, l = tid & 31;
    const int wm = w >> 1, wn = w & 1;
    const int lr = l >> 2, lc = l & 3;

    const uint32_t as_base = (uint32_t)__cvta_generic_to_shared(&As[0][0][0]);
    const uint32_t bs_base = (uint32_t)__cvta_generic_to_shared(&Bs[0][0][0]);
    const int ld_r = (tid >> 2);
    const int ld_q = (tid & 3) * 4;

    float acc[2][8][4] = {};

#pragma unroll
    for (int i = 0; i < 2; i++) {
        int r = ld_r + 64 * i;
        CP_ASYNC16(as_base + (uint32_t)((r * 20 + ld_q) * 4),
                   &x[(size_t)(m0 + r) * INPUT + ld_q]);
        CP_ASYNC16(bs_base + (uint32_t)((r * 20 + ld_q) * 4),
                   &Wih[(size_t)(n0 + r) * INPUT + ld_q]);
    }
    CP_COMMIT;

    for (int ks = 0; ks < 16; ks++) {
        const int s = ks & 1;
        if (ks + 1 < 16) {
            const int s2 = (ks + 1) & 1;
            const int k0 = (ks + 1) * 16;
#pragma unroll
            for (int i = 0; i < 2; i++) {
                int r = ld_r + 64 * i;
                CP_ASYNC16(as_base + (uint32_t)(((s2 * 128 + r) * 20 + ld_q) * 4),
                           &x[(size_t)(m0 + r) * INPUT + k0 + ld_q]);
                CP_ASYNC16(bs_base + (uint32_t)(((s2 * 128 + r) * 20 + ld_q) * 4),
                           &Wih[(size_t)(n0 + r) * INPUT + k0 + ld_q]);
            }
            CP_COMMIT;
            CP_WAIT1;
        } else {
            CP_WAIT0;
        }
        __syncthreads();

#pragma unroll
        for (int kk = 0; kk < 16; kk += 8) {
            uint32_t a[2][4], b[8][2];
#pragma unroll
            for (int mt = 0; mt < 2; mt++) {
                int r = wm * 32 + mt * 16 + lr;
                a[mt][0] = f2tf(As[s][r][kk + lc]);
                a[mt][1] = f2tf(As[s][r + 8][kk + lc]);
                a[mt][2] = f2tf(As[s][r][kk + lc + 4]);
                a[mt][3] = f2tf(As[s][r + 8][kk + lc + 4]);
            }
#pragma unroll
            for (int nt = 0; nt < 8; nt++) {
                int n = wn * 64 + nt * 8 + lr;
                b[nt][0] = f2tf(Bs[s][n][kk + lc]);
                b[nt][1] = f2tf(Bs[s][n][kk + lc + 4]);
            }
#pragma unroll
            for (int mt = 0; mt < 2; mt++)
#pragma unroll
                for (int nt = 0; nt < 8; nt++)
                    mma_tf32(acc[mt][nt], a[mt], b[nt]);
        }
        __syncthreads();
    }

#pragma unroll
    for (int nt = 0; nt < 8; nt++) {
        int col = n0 + wn * 64 + nt * 8 + 2 * lc;
        float bias0 = bih[col] + bhh[col];
        float bias1 = bih[col + 1] + bhh[col + 1];
#pragma unroll
        for (int mt = 0; mt < 2; mt++) {
            int r0 = m0 + wm * 32 + mt * 16 + lr;
            int r1 = r0 + 8;
            size_t o0 = ((size_t)(r0 & (SEQ - 1)) * BATCH + (r0 >> 9)) * G4 + col;
            size_t o1 = ((size_t)(r1 & (SEQ - 1)) * BATCH + (r1 >> 9)) * G4 + col;
            g_xproj[o0]     = acc[mt][nt][0] + bias0;
            g_xproj[o0 + 1] = acc[mt][nt][1] + bias1;
            g_xproj[o1]     = acc[mt][nt][2] + bias0;
            g_xproj[o1 + 1] = acc[mt][nt][3] + bias1;
        }
    }
}

// ---------------- phase 2: persistent LSTM scan (64 CTAs) ----------------
// CTA (bx in 0..15, by in 0..3): j-slice of 32 units, batch group of 64 rows.
// Per step: gates[64, 128 = 4 gates x 32 units] = h[64,512] @ Whh_slice[128,512]^T.
// W slice persistent in smem (133 KB); gate-staging buffer ALIASED onto h buffer.
#define HS_LD 520
#define GS_LD 132
#define WS_BYTES (128 * HS_LD * 2)                 // 133120
#define HS_BYTES (BW * HS_LD * 2)                  // 66560
#define SMEM_STEP (WS_BYTES + HS_BYTES)            // 199680

__global__ __launch_bounds__(256) void lstm_scan_kernel() {
    extern __shared__ char smraw[];
    __nv_bfloat16* ws = (__nv_bfloat16*)smraw;               // [128][HS_LD] persistent W slice
    __nv_bfloat16* hs = (__nv_bfloat16*)(smraw + WS_BYTES);  // [64][HS_LD] h tile
    float* gs = (float*)hs;                                   // [64][GS_LD] ALIAS (disjoint live range)

    const int bx = blockIdx.x, by = blockIdx.y;
    const int j0 = bx * JW;
    const int b0 = by * BW;
    const int tid = threadIdx.x;
    const int w = tid >> 5, l = tid & 31;
    const int wm = w >> 2, wn = w & 3;              // 2x4 warp grid, warp tile 32x32
    const int lr = l >> 2, lc2 = (l & 3) * 2;
    const int bb = tid >> 2;                         // epilogue batch row (0..63)
    const int u0 = (tid & 3) * 8;                    // epilogue unit base (8 units)

    // ---- load W slice once: row r = gate*32 + unit ----
#pragma unroll
    for (int i = 0; i < 32; i++) {
        int idx = tid + 256 * i;
        int r = idx >> 6, q = (idx & 63) * 8;
        int gi = r >> 5, uu = r & 31;
        *(float4*)&ws[r * HS_LD + q] =
            *(const float4*)&g_Whh_bf[(size_t)(gi * HID + j0 + uu) * HID + q];
    }

    // ---- ldmatrix addresses ----
    const uint32_t hs_base = (uint32_t)__cvta_generic_to_shared(hs);
    const uint32_t ws_base = (uint32_t)__cvta_generic_to_shared(ws);
    const uint32_t a_addr0 = hs_base +
        (uint32_t)(((wm * 32 + (l & 15)) * HS_LD + ((l >> 4) * 8)) * 2);
    const uint32_t a_addr1 = a_addr0 + 16 * HS_LD * 2;
    const uint32_t b_addr0 = ws_base +
        (uint32_t)(((wn * 32 + (l & 7) + ((l >> 4) << 3)) * HS_LD + (((l >> 3) & 1) * 8)) * 2);
    const uint32_t b_addr1 = b_addr0 + 16 * HS_LD * 2;

    float c_reg[8] = {};
    float xi[8], xf[8], xg[8], xo[8];               // prefetched x_proj for current step

    // prefetch t = 0
    {
        const float* xr = g_xproj + (size_t)(b0 + bb) * G4 + (j0 + u0);
        *(float4*)&xi[0] = *(const float4*)(xr);           *(float4*)&xi[4] = *(const float4*)(xr + 4);
        *(float4*)&xf[0] = *(const float4*)(xr + HID);     *(float4*)&xf[4] = *(const float4*)(xr + HID + 4);
        *(float4*)&xg[0] = *(const float4*)(xr + 2*HID);   *(float4*)&xg[4] = *(const float4*)(xr + 2*HID + 4);
        *(float4*)&xo[0] = *(const float4*)(xr + 3*HID);   *(float4*)&xo[4] = *(const float4*)(xr + 3*HID + 4);
    }
    __syncthreads();                                 // ws loaded

    for (int t = 0; t < SEQ; t++) {
        // ---- h fill via cp.async, two K-halves ----
        const __nv_bfloat16* hsrc = g_hbuf[t & 1] + (size_t)b0 * HID;
#pragma unroll
        for (int i = 0; i < 8; i++) {
            int idx = tid + 256 * i;
            int r = idx >> 5, q = (idx & 31) * 8;
            CP_ASYNC16(hs_base + (uint32_t)((r * HS_LD + q) * 2), &hsrc[r * HID + q]);
        }
        CP_COMMIT;
#pragma unroll
        for (int i = 0; i < 8; i++) {
            int idx = tid + 256 * i;
            int r = idx >> 5, q = (idx & 31) * 8 + 256;
            CP_ASYNC16(hs_base + (uint32_t)((r * HS_LD + q) * 2), &hsrc[r * HID + q]);
        }
        CP_COMMIT;

        float acc[2][4][4] = {};
        CP_WAIT1;
        __syncthreads();
#pragma unroll 4
        for (int k0 = 0; k0 < 16; k0++) {            // K 0..255
            const uint32_t kofs = (uint32_t)(k0 * 32);
            uint32_t a[2][4], b[4][2];
            ldsm_x4(a[0][0], a[0][1], a[0][2], a[0][3], a_addr0 + kofs);
            ldsm_x4(a[1][0], a[1][1], a[1][2], a[1][3], a_addr1 + kofs);
            ldsm_x4(b[0][0], b[0][1], b[1][0], b[1][1], b_addr0 + kofs);
            ldsm_x4(b[2][0], b[2][1], b[3][0], b[3][1], b_addr1 + kofs);
#pragma unroll
            for (int mt = 0; mt < 2; mt++)
#pragma unroll
                for (int nt = 0; nt < 4; nt++)
                    mma_bf16(acc[mt][nt], a[mt], b[nt]);
        }
        CP_WAIT0;
        __syncthreads();
#pragma unroll 4
        for (int k0 = 16; k0 < 32; k0++) {           // K 256..511
            const uint32_t kofs = (uint32_t)(k0 * 32);
            uint32_t a[2][4], b[4][2];
            ldsm_x4(a[0][0], a[0][1], a[0][2], a[0][3], a_addr0 + kofs);
            ldsm_x4(a[1][0], a[1][1], a[1][2], a[1][3], a_addr1 + kofs);
            ldsm_x4(b[0][0], b[0][1], b[1][0], b[1][1], b_addr0 + kofs);
            ldsm_x4(b[2][0], b[2][1], b[3][0], b[3][1], b_addr1 + kofs);
#pragma unroll
            for (int mt = 0; mt < 2; mt++)
#pragma unroll
                for (int nt = 0; nt < 4; nt++)
                    mma_bf16(acc[mt][nt], a[mt], b[nt]);
        }
        __syncthreads();                             // all warps done reading hs (gs aliases it)

        // ---- stage gates to smem ----
#pragma unroll
        for (int mt = 0; mt < 2; mt++) {
            int row = wm * 32 + mt * 16 + lr;
#pragma unroll
            for (int nt = 0; nt < 4; nt++) {
                int col = wn * 32 + nt * 8 + lc2;
                *(float2*)&gs[row * GS_LD + col]       = make_float2(acc[mt][nt][0], acc[mt][nt][1]);
                *(float2*)&gs[(row + 8) * GS_LD + col] = make_float2(acc[mt][nt][2], acc[mt][nt][3]);
            }
        }
        __syncthreads();

        // ---- epilogue: 8 cells per thread (row bb, units u0..u0+7) ----
        float gi_[8], gf_[8], gg_[8], go_[8];
        {
            const float* gr = gs + bb * GS_LD;
            *(float4*)&gi_[0] = *(const float4*)&gr[u0];            *(float4*)&gi_[4] = *(const float4*)&gr[u0 + 4];
            *(float4*)&gf_[0] = *(const float4*)&gr[32 + u0];       *(float4*)&gf_[4] = *(const float4*)&gr[32 + u0 + 4];
            *(float4*)&gg_[0] = *(const float4*)&gr[64 + u0];       *(float4*)&gg_[4] = *(const float4*)&gr[64 + u0 + 4];
            *(float4*)&go_[0] = *(const float4*)&gr[96 + u0];       *(float4*)&go_[4] = *(const float4*)&gr[96 + u0 + 4];
        }
        float hval[8];
#pragma unroll
        for (int v = 0; v < 8; v++) {
            float ig = fsigmoid(gi_[v] + xi[v]);
            float fg = fsigmoid(gf_[v] + xf[v]);
            float gv = ftanh(gg_[v] + xg[v]);
            float og = fsigmoid(go_[v] + xo[v]);
            float c = fg * c_reg[v] + ig * gv;
            c_reg[v] = c;
            hval[v] = og * ftanh(c);
        }
        const size_t oidx = (size_t)(b0 + bb) * HID + (j0 + u0);
        if (t == SEQ - 1) {
            *(float4*)&g_hlast[oidx]     = make_float4(hval[0], hval[1], hval[2], hval[3]);
            *(float4*)&g_hlast[oidx + 4] = make_float4(hval[4], hval[5], hval[6], hval[7]);
        } else {
            __nv_bfloat16* hdst = g_hbuf[(t + 1) & 1];
            __nv_bfloat162 p0 = __floats2bfloat162_rn(hval[0], hval[1]);
            __nv_bfloat162 p1 = __floats2bfloat162_rn(hval[2], hval[3]);
            __nv_bfloat162 p2 = __floats2bfloat162_rn(hval[4], hval[5]);
            __nv_bfloat162 p3 = __floats2bfloat162_rn(hval[6], hval[7]);
            uint4 pkt;
            pkt.x = *(uint32_t*)&p0; pkt.y = *(uint32_t*)&p1;
            pkt.z = *(uint32_t*)&p2; pkt.w = *(uint32_t*)&p3;
            *(uint4*)&hdst[oidx] = pkt;

            // ---- barrier: release, prefetch next xproj, poll ----
            __syncthreads();                         // all h stores issued CTA-wide
            if (tid == 0) {
                asm volatile("st.release.gpu.global.u32 [%0], %1;"
                             :: "l"(&g_flags[by][bx]), "r"((unsigned)(t + 1)) : "memory");
            }
            {   // prefetch x_proj(t+1) while peers finish
                const float* xr = g_xproj + ((size_t)(t + 1) * BATCH + (b0 + bb)) * G4 + (j0 + u0);
                *(float4*)&xi[0] = *(const float4*)(xr);           *(float4*)&xi[4] = *(const float4*)(xr + 4);
                *(float4*)&xf[0] = *(const float4*)(xr + HID);     *(float4*)&xf[4] = *(const float4*)(xr + HID + 4);
                *(float4*)&xg[0] = *(const float4*)(xr + 2*HID);   *(float4*)&xg[4] = *(const float4*)(xr + 2*HID + 4);
                *(float4*)&xo[0] = *(const float4*)(xr + 3*HID);   *(float4*)&xo[4] = *(const float4*)(xr + 3*HID + 4);
            }
            if (tid < NJ) {
                unsigned v;
                do {
                    asm volatile("ld.relaxed.gpu.global.u32 %0, [%1];"
                                 : "=r"(v) : "l"(&g_flags[by][tid]) : "memory");
                } while (v < (unsigned)(t + 1));
                asm volatile("fence.acq_rel.gpu;" ::: "memory");
            }
            __syncthreads();
        }
    }
}

// ---------------- phase 3: FC head ----------------
#define FC_LD 516
#define SMEM_FC (2 * 16 * FC_LD * 4)
__global__ __launch_bounds__(256) void fc_kernel(const float* __restrict__ Wfc,
                                                 const float* __restrict__ bfc,
                                                 float* __restrict__ out) {
    extern __shared__ float fcsm[];
    float* hsm = fcsm;
    float* wsm = fcsm + 16 * FC_LD;
    const int cg = blockIdx.x * 16, bg = blockIdx.y * 16;
    const int tid = threadIdx.x;
    {
        int r = tid >> 4, q = (tid & 15) * 4;
#pragma unroll
        for (int i = 0; i < 8; i++) {
            *(float4*)&hsm[r * FC_LD + q + 64 * i] =
                *(const float4*)&g_hlast[(size_t)(bg + r) * HID + q + 64 * i];
            *(float4*)&wsm[r * FC_LD + q + 64 * i] =
                *(const float4*)&Wfc[(size_t)(cg + r) * HID + q + 64 * i];
        }
    }
    __syncthreads();
    const int c = tid & 15, b = tid >> 4;
    float acc = bfc[cg + c];
#pragma unroll 8
    for (int k = 0; k < HID; k += 4) {
        float4 wv = *(float4*)&wsm[c * FC_LD + k];
        float4 hv = *(float4*)&hsm[b * FC_LD + k];
        acc += hv.x * wv.x + hv.y * wv.y + hv.z * wv.z + hv.w * wv.w;
    }
    out[(size_t)(bg + b) * NCLS + cg + c] = acc;
}

// ---------------- launch ----------------
extern "C" void kernel_launch(void* const* d_in, const int* in_sizes, int n_in,
                              void* d_out, int out_size) {
    const float* x   = (const float*)d_in[0];
    const float* Wih = (const float*)d_in[1];
    const float* Whh = (const float*)d_in[2];
    const float* bih = (const float*)d_in[3];
    const float* bhh = (const float*)d_in[4];
    const float* Wfc = (const float*)d_in[5];
    const float* bfc = (const float*)d_in[6];
    float* out = (float*)d_out;

    cudaFuncSetAttribute(lstm_scan_kernel, cudaFuncAttributeMaxDynamicSharedMemorySize, SMEM_STEP);
    cudaFuncSetAttribute(fc_kernel, cudaFuncAttributeMaxDynamicSharedMemorySize, SMEM_FC);

    setup_kernel<<<1024, 256>>>(Whh);
    dummy_kernel<<<1, 32>>>();                      // pad launches so ncu -s 5 -c 1
    dummy_kernel<<<1, 32>>>();                      // samples the scan kernel (launch #6)
    dummy_kernel<<<1, 32>>>();

    dim3 gx(G4 / 128, (BATCH * SEQ) / 128);
    xproj_kernel<<<gx, 256>>>(x, Wih, bih, bhh);

    lstm_scan_kernel<<<dim3(NJ, NB), 256, SMEM_STEP>>>();

    fc_kernel<<<dim3(NCLS / 16, BATCH / 16), 256, SMEM_FC>>>(Wfc, bfc, out);
}